// round 16
// baseline (speedup 1.0000x reference)
#include <cuda_runtime.h>
#include <cfloat>
#include <cstdint>

#define BB 8
#define NN 16384
#define SS 2048
#define DD 64

__device__ float g_pnorm[BB * NN];
__device__ int   g_topk[BB * SS * 32];
__device__ float g_h2[BB * NN * 128];
__device__ float g_w0f[64 * 64], g_w1f[64 * 64], g_w2f[128 * 64];
__device__ float g_b0f[64], g_b1f[64], g_b2f[128];
__device__ unsigned long long g_wp[8192];   // packed: [0,2048) w0, [2048,4096) w1, [4096,8192) w2

// ---------------- packed f32x2 + cp.async helpers ----------------
__device__ __forceinline__ uint32_t smem_u32(const void* p) {
    uint32_t a;
    asm("{ .reg .u64 t; cvta.to.shared.u64 t, %1; cvt.u32.u64 %0, t; }" : "=r"(a) : "l"(p));
    return a;
}
__device__ __forceinline__ unsigned long long pk2(float x, float y) {
    unsigned long long r;
    asm("mov.b64 %0, {%1,%2};" : "=l"(r) : "f"(x), "f"(y));
    return r;
}
__device__ __forceinline__ void upk2(float& x, float& y, unsigned long long v) {
    asm("mov.b64 {%0,%1}, %2;" : "=f"(x), "=f"(y) : "l"(v));
}
__device__ __forceinline__ void fmax2(unsigned long long& a, unsigned long long b,
                                      unsigned long long c) {
    asm("fma.rn.f32x2 %0, %1, %2, %0;" : "+l"(a) : "l"(b), "l"(c));
}
__device__ __forceinline__ unsigned long long addx2(unsigned long long a,
                                                    unsigned long long b) {
    unsigned long long r;
    asm("add.rn.f32x2 %0, %1, %2;" : "=l"(r) : "l"(a), "l"(b));
    return r;
}
#define CPA16(dst, src) \
    asm volatile("cp.async.cg.shared.global [%0], [%1], 16;" :: "r"(dst), "l"(src))
#define CPA4(dst, src) \
    asm volatile("cp.async.ca.shared.global [%0], [%1], 4;" :: "r"(dst), "l"(src))
#define CPA_COMMIT() asm volatile("cp.async.commit_group;" ::: "memory")
#define CPA_WAIT1()  asm volatile("cp.async.wait_group 1;" ::: "memory")
#define QBAR(q) asm volatile("bar.sync %0, 128;" :: "r"((q) + 1) : "memory")

// ---------------- weight/BN folding + f32x2 packing ----------------
__global__ void k_prep(const float* __restrict__ w0, const float* __restrict__ b0,
                       const float* __restrict__ gg0, const float* __restrict__ be0,
                       const float* __restrict__ m0, const float* __restrict__ v0,
                       const float* __restrict__ w1, const float* __restrict__ b1,
                       const float* __restrict__ gg1, const float* __restrict__ be1,
                       const float* __restrict__ m1, const float* __restrict__ v1,
                       const float* __restrict__ w2, const float* __restrict__ b2,
                       const float* __restrict__ gg2, const float* __restrict__ be2,
                       const float* __restrict__ m2, const float* __restrict__ v2) {
    int o = threadIdx.x;
    if (o < 64) {
        float s0 = gg0[o] * rsqrtf(v0[o] + 1e-5f);
        for (int c = 0; c < 64; c++) g_w0f[o * 64 + c] = w0[o * 64 + c] * s0;
        g_b0f[o] = (b0[o] - m0[o]) * s0 + be0[o];
        float s1 = gg1[o] * rsqrtf(v1[o] + 1e-5f);
        for (int c = 0; c < 64; c++) g_w1f[o * 64 + c] = w1[o * 64 + c] * s1;
        g_b1f[o] = (b1[o] - m1[o]) * s1 + be1[o];
        for (int j = 0; j < 32; j++) {
            g_wp[o * 32 + j]        = pk2(g_w0f[o * 64 + 2 * j], g_w0f[o * 64 + 2 * j + 1]);
            g_wp[2048 + o * 32 + j] = pk2(g_w1f[o * 64 + 2 * j], g_w1f[o * 64 + 2 * j + 1]);
        }
    }
    float s2 = gg2[o] * rsqrtf(v2[o] + 1e-5f);
    for (int c = 0; c < 64; c++) g_w2f[o * 64 + c] = w2[o * 64 + c] * s2;
    g_b2f[o] = (b2[o] - m2[o]) * s2 + be2[o];
    for (int j = 0; j < 32; j++)
        g_wp[4096 + o * 32 + j] = pk2(g_w2f[o * 64 + 2 * j], g_w2f[o * 64 + 2 * j + 1]);
}

__global__ void k_pnorm(const float* __restrict__ points) {
    int i = blockIdx.x * blockDim.x + threadIdx.x;
    const float4* p = (const float4*)(points + (size_t)i * DD);
    float a0 = 0, a1 = 0, a2 = 0, a3 = 0;
#pragma unroll
    for (int u = 0; u < 16; u++) {
        float4 v = p[u];
        a0 = fmaf(v.x, v.x, a0); a1 = fmaf(v.y, v.y, a1);
        a2 = fmaf(v.z, v.z, a2); a3 = fmaf(v.w, v.w, a3);
    }
    g_pnorm[i] = (a0 + a1) + (a2 + a3);
}

__global__ void k_newxyz(const float* __restrict__ xyz, const int* __restrict__ sidx,
                         float* __restrict__ out) {
    int t = blockIdx.x * blockDim.x + threadIdx.x;
    if (t >= BB * SS * 3) return;
    int c = t % 3, s = (t / 3) % SS, b = t / (3 * SS);
    out[t] = xyz[((size_t)b * NN + sidx[s]) * 3 + c];
}

// ============================================================================
// k_mlp2: unchanged R12 winner (f32x2, smem weights, 2 CTAs/SM)
// ============================================================================
#define MLP_SMEMB (8192 * 8 + 32 * 129 * 4)

__device__ __forceinline__ void mlp_layer64(const unsigned long long* __restrict__ wsm,
                                            const float* __restrict__ bias,
                                            const unsigned long long* ip,
                                            unsigned long long* op) {
#pragma unroll 4
    for (int o2 = 0; o2 < 32; o2++) {
        const ulonglong2* r0 = (const ulonglong2*)(wsm + (2 * o2) * 32);
        const ulonglong2* r1 = (const ulonglong2*)(wsm + (2 * o2 + 1) * 32);
        unsigned long long a0 = 0ull, a1 = 0ull, b0 = 0ull, b1 = 0ull;
#pragma unroll
        for (int i = 0; i < 16; i++) {
            ulonglong2 w0v = r0[i];
            ulonglong2 w1v = r1[i];
            fmax2(a0, ip[2 * i], w0v.x);
            fmax2(a1, ip[2 * i + 1], w0v.y);
            fmax2(b0, ip[2 * i], w1v.x);
            fmax2(b1, ip[2 * i + 1], w1v.y);
        }
        float c0, c1, c2, c3;
        upk2(c0, c1, a0); upk2(c2, c3, a1);
        float s0 = (c0 + c1) + (c2 + c3);
        upk2(c0, c1, b0); upk2(c2, c3, b1);
        float s1 = (c0 + c1) + (c2 + c3);
        op[o2] = pk2(fmaxf(s0 + __ldg(bias + 2 * o2), 0.f),
                     fmaxf(s1 + __ldg(bias + 2 * o2 + 1), 0.f));
    }
}

__global__ void __launch_bounds__(128, 2) k_mlp2(const float* __restrict__ points) {
    extern __shared__ unsigned long long msm[];
    float* stg = (float*)(msm + 8192);
    const int tid = threadIdx.x;
    const size_t pt = (size_t)blockIdx.x * 128 + tid;

    for (int i = tid; i < 8192; i += 128) msm[i] = g_wp[i];

    unsigned long long xp[32];
    {
        const float4* x4 = (const float4*)(points + pt * DD);
#pragma unroll
        for (int u = 0; u < 16; u++) {
            float4 v = x4[u];
            xp[2 * u]     = pk2(v.x, v.y);
            xp[2 * u + 1] = pk2(v.z, v.w);
        }
    }
    __syncthreads();

    unsigned long long h0[32], h1[32];
    mlp_layer64(msm,        g_b0f, xp, h0);
    mlp_layer64(msm + 2048, g_b1f, h0, h1);

    const size_t obase = (size_t)blockIdx.x * 128 * 128;
    const int lane = tid & 31, grp = tid >> 5;
    for (int ch = 0; ch < 4; ch++) {
        __syncthreads();
#pragma unroll 2
        for (int o2 = 0; o2 < 16; o2++) {
            const int o = ch * 32 + 2 * o2;
            const ulonglong2* r0 = (const ulonglong2*)(msm + 4096 + o * 32);
            const ulonglong2* r1 = (const ulonglong2*)(msm + 4096 + (o + 1) * 32);
            unsigned long long a0 = 0ull, a1 = 0ull, b0 = 0ull, b1 = 0ull;
#pragma unroll
            for (int i = 0; i < 16; i++) {
                ulonglong2 w0v = r0[i];
                ulonglong2 w1v = r1[i];
                fmax2(a0, h1[2 * i], w0v.x);
                fmax2(a1, h1[2 * i + 1], w0v.y);
                fmax2(b0, h1[2 * i], w1v.x);
                fmax2(b1, h1[2 * i + 1], w1v.y);
            }
            float c0, c1, c2, c3;
            upk2(c0, c1, a0); upk2(c2, c3, a1);
            float s0 = (c0 + c1) + (c2 + c3);
            upk2(c0, c1, b0); upk2(c2, c3, b1);
            float s1 = (c0 + c1) + (c2 + c3);
            stg[(2 * o2 + 0) * 129 + tid] = fmaxf(s0 + __ldg(g_b2f + o), 0.f);
            stg[(2 * o2 + 1) * 129 + tid] = fmaxf(s1 + __ldg(g_b2f + o + 1), 0.f);
        }
        __syncthreads();
#pragma unroll 4
        for (int rr = grp; rr < 128; rr += 4) {
            g_h2[obase + (size_t)rr * 128 + ch * 32 + lane] = stg[lane * 129 + rr];
        }
    }
}

// ============================================================================
// k_dist9: R14 math + per-quarter producers + NAMED barriers (decorrelated)
// ============================================================================
#define DS_SP  0u
#define DS_PN  16384u
#define DS_TV  16640u
#define DS_TI  33536u
#define DS_TOTB (50432 * 4)

struct TkMeta {
    float g0, g1, g2, g3;
    int   s0, s1, s2, s3;
    float thr;
    int   esl;
};
__device__ __forceinline__ void tk_init(TkMeta& M) {
    M.g0 = M.g1 = M.g2 = M.g3 = FLT_MAX;
    M.s0 = 0; M.s1 = 8; M.s2 = 16; M.s3 = 24;
    M.thr = FLT_MAX; M.esl = 0;
}
__device__ __forceinline__ void tk_insert(float* lv, int* li, float sc, int idx, TkMeta& M) {
    lv[M.esl] = sc; li[M.esl] = idx;
    const int g = M.esl >> 3;
    const int base = g << 3;
    float m = lv[base]; int ms = base;
#pragma unroll
    for (int j = 1; j < 8; j++) {
        float v = lv[base + j];
        if (v > m) { m = v; ms = base + j; }
    }
    if (g == 0)      { M.g0 = m; M.s0 = ms; }
    else if (g == 1) { M.g1 = m; M.s1 = ms; }
    else if (g == 2) { M.g2 = m; M.s2 = ms; }
    else             { M.g3 = m; M.s3 = ms; }
    float t = M.g0; int e = M.s0;
    if (M.g1 > t) { t = M.g1; e = M.s1; }
    if (M.g2 > t) { t = M.g2; e = M.s2; }
    if (M.g3 > t) { t = M.g3; e = M.s3; }
    M.thr = t; M.esl = e;
}

__global__ void __launch_bounds__(512, 1) k_dist9(const float* __restrict__ points,
                                                  const int* __restrict__ sidx) {
    extern __shared__ float dsm[];
    const uint32_t sb = smem_u32(dsm);
    const int tid = threadIdx.x;
    const int qh = tid >> 7, l128 = tid & 127;
    const int b = blockIdx.y, s0 = blockIdx.x * 128;

    float* lv = dsm + DS_TV + tid * 33;
    int*   li = (int*)(dsm + DS_TI) + tid * 33;

    unsigned long long q2[32];
    {
        const int qi = __ldg(sidx + s0 + l128);
        const float4* qp = (const float4*)(points + ((size_t)b * NN + qi) * DD);
#pragma unroll
        for (int u = 0; u < 16; u++) {
            float4 v = qp[u];
            q2[2 * u]     = pk2(2.f * v.x, 2.f * v.y);
            q2[2 * u + 1] = pk2(2.f * v.z, 2.f * v.w);
        }
    }
#pragma unroll
    for (int j = 0; j < 32; j++) lv[j] = FLT_MAX;
    TkMeta M;
    tk_init(M);

    const float4* Pb = (const float4*)(points + (size_t)b * NN * DD);
    const float*  Pn = g_pnorm + b * NN;

    // quarter-local staging: quarter qh loads its own 8KB slice + its 32 pnorms
    // dst bytes: buf*32768 + qh*8192 + l128*16 + i*2048 ; src float4: t*2048 + qh*512 + i*128 + l128
    {
        uint32_t d = sb + qh * 8192u + l128 * 16u;
        const float4* s = Pb + qh * 512 + l128;
#pragma unroll
        for (int i = 0; i < 4; i++) CPA16(d + i * 2048u, s + i * 128);
        if (l128 < 32) CPA4(sb + (DS_PN + qh * 32u + l128) * 4, Pn + qh * 32 + l128);
    }
    CPA_COMMIT();

    for (int t = 0; t < 128; t++) {
        const int cur = t & 1;
        if (t < 127) {
            const int nxt = cur ^ 1;
            uint32_t d = sb + nxt * 32768u + qh * 8192u + l128 * 16u;
            const float4* s = Pb + (size_t)(t + 1) * 2048 + qh * 512 + l128;
#pragma unroll
            for (int i = 0; i < 4; i++) CPA16(d + i * 2048u, s + i * 128);
            if (l128 < 32)
                CPA4(sb + (DS_PN + nxt * 128u + qh * 32u + l128) * 4,
                     Pn + (t + 1) * 128 + qh * 32 + l128);
        }
        CPA_COMMIT();
        CPA_WAIT1();
        QBAR(qh);                               // quarter's data visible

        const float* tp = dsm + DS_SP + cur * 8192 + qh * 2048;
        const float* pn = dsm + DS_PN + cur * 128 + qh * 32;
        const int ibase = t * 128 + qh * 32;
#pragma unroll 4
        for (int p = 0; p < 32; p++) {
            const ulonglong2* pv = (const ulonglong2*)(tp + p * 64);
            unsigned long long a0 = 0ull, a1 = 0ull;
#pragma unroll
            for (int i = 0; i < 16; i++) {
                ulonglong2 w = pv[i];
                fmax2(a0, q2[2 * i], w.x);
                fmax2(a1, q2[2 * i + 1], w.y);
            }
            a0 = addx2(a0, a1);
            float lo, hi;
            upk2(lo, hi, a0);
            float sc = pn[p] - (lo + hi);
            if (sc < M.thr) tk_insert(lv, li, sc, ibase + p, M);
        }
        QBAR(qh);                               // quarter done reading buf[cur]
    }

    __syncthreads();   // cross-quarter: all lists final before merge
    if (tid < 128) {
        float* stv = dsm + DS_TV;
        int*   sti = (int*)(dsm + DS_TI);
        int* op = g_topk + ((size_t)b * SS + s0 + tid) * 32;
        for (int k = 0; k < 32; k++) {
            float m = FLT_MAX; int mi = 0x7fffffff, sel = 0;
#pragma unroll
            for (int h = 0; h < 4; h++) {
                const int base = (tid + 128 * h) * 33;
                for (int j = 0; j < 32; j++) {
                    float v = stv[base + j];
                    int   ii = sti[base + j];
                    if (v < m || (v == m && ii < mi)) { m = v; mi = ii; sel = base + j; }
                }
            }
            op[k] = mi;
            stv[sel] = FLT_MAX;
        }
    }
}

// ---------------- gather + channel max over the 32 neighbors ----------------
__global__ void k_gmax(float* __restrict__ out) {
    const int b = blockIdx.y, s = blockIdx.x, c = threadIdx.x;
    __shared__ int si[32];
    if (threadIdx.x < 32) si[threadIdx.x] = g_topk[((size_t)b * SS + s) * 32 + threadIdx.x];
    __syncthreads();
    const float* hb = g_h2 + (size_t)b * NN * 128;
    float m = -FLT_MAX;
#pragma unroll 8
    for (int j = 0; j < 32; j++) m = fmaxf(m, hb[(size_t)si[j] * 128 + c]);
    out[((size_t)b * SS + s) * 128 + c] = m;
}

// ---------------- launch ----------------
extern "C" void kernel_launch(void* const* d_in, const int* in_sizes, int n_in,
                              void* d_out, int out_size) {
    const float* xyz    = (const float*)d_in[0];
    const float* points = (const float*)d_in[1];
    const int*   sidx   = (const int*)d_in[2];

    float* out = (float*)d_out;
    float* out_xyz = nullptr;
    float* out_pts = out;
    if (out_size == BB * SS * 3 + BB * SS * 128) {
        out_xyz = out;
        out_pts = out + BB * SS * 3;
    }

    cudaFuncSetAttribute(k_dist9, cudaFuncAttributeMaxDynamicSharedMemorySize, DS_TOTB);
    cudaFuncSetAttribute(k_mlp2, cudaFuncAttributeMaxDynamicSharedMemorySize, MLP_SMEMB);

    k_prep<<<1, 128>>>((const float*)d_in[3], (const float*)d_in[4], (const float*)d_in[5],
                       (const float*)d_in[6], (const float*)d_in[7], (const float*)d_in[8],
                       (const float*)d_in[9], (const float*)d_in[10], (const float*)d_in[11],
                       (const float*)d_in[12], (const float*)d_in[13], (const float*)d_in[14],
                       (const float*)d_in[15], (const float*)d_in[16], (const float*)d_in[17],
                       (const float*)d_in[18], (const float*)d_in[19], (const float*)d_in[20]);
    k_pnorm<<<(BB * NN) / 256, 256>>>(points);
    if (out_xyz)
        k_newxyz<<<(BB * SS * 3 + 127) / 128, 128>>>(xyz, sidx, out_xyz);
    k_dist9<<<dim3(SS / 128, BB), 512, DS_TOTB>>>(points, sidx);
    k_mlp2<<<(BB * NN) / 128, 128, MLP_SMEMB>>>(points);
    k_gmax<<<dim3(SS, BB), 128>>>(out_pts);
}

// round 17
// speedup vs baseline: 1.5997x; 1.5997x over previous
#include <cuda_runtime.h>
#include <cfloat>
#include <cstdint>

#define BB 8
#define NN 16384
#define SS 2048
#define DD 64

__device__ float g_pnorm[BB * NN];
__device__ int   g_topk[BB * SS * 32];
__device__ float g_h2[BB * NN * 128];
__device__ float g_w0f[64 * 64], g_w1f[64 * 64], g_w2f[128 * 64];
__device__ float g_b0f[64], g_b1f[64], g_b2f[128];
__device__ unsigned long long g_wp[8192];   // packed: [0,2048) w0, [2048,4096) w1, [4096,8192) w2

// ---------------- packed f32x2 + cp.async helpers ----------------
__device__ __forceinline__ uint32_t smem_u32(const void* p) {
    uint32_t a;
    asm("{ .reg .u64 t; cvta.to.shared.u64 t, %1; cvt.u32.u64 %0, t; }" : "=r"(a) : "l"(p));
    return a;
}
__device__ __forceinline__ unsigned long long pk2(float x, float y) {
    unsigned long long r;
    asm("mov.b64 %0, {%1,%2};" : "=l"(r) : "f"(x), "f"(y));
    return r;
}
__device__ __forceinline__ void upk2(float& x, float& y, unsigned long long v) {
    asm("mov.b64 {%0,%1}, %2;" : "=f"(x), "=f"(y) : "l"(v));
}
__device__ __forceinline__ void fmax2(unsigned long long& a, unsigned long long b,
                                      unsigned long long c) {
    asm("fma.rn.f32x2 %0, %1, %2, %0;" : "+l"(a) : "l"(b), "l"(c));
}
__device__ __forceinline__ unsigned long long addx2(unsigned long long a,
                                                    unsigned long long b) {
    unsigned long long r;
    asm("add.rn.f32x2 %0, %1, %2;" : "=l"(r) : "l"(a), "l"(b));
    return r;
}
#define CPA16(dst, src) \
    asm volatile("cp.async.cg.shared.global [%0], [%1], 16;" :: "r"(dst), "l"(src))
#define CPA4(dst, src) \
    asm volatile("cp.async.ca.shared.global [%0], [%1], 4;" :: "r"(dst), "l"(src))
#define CPA_COMMIT() asm volatile("cp.async.commit_group;" ::: "memory")
#define CPA_WAIT1()  asm volatile("cp.async.wait_group 1;" ::: "memory")

// ---------------- weight/BN folding + f32x2 packing ----------------
__global__ void k_prep(const float* __restrict__ w0, const float* __restrict__ b0,
                       const float* __restrict__ gg0, const float* __restrict__ be0,
                       const float* __restrict__ m0, const float* __restrict__ v0,
                       const float* __restrict__ w1, const float* __restrict__ b1,
                       const float* __restrict__ gg1, const float* __restrict__ be1,
                       const float* __restrict__ m1, const float* __restrict__ v1,
                       const float* __restrict__ w2, const float* __restrict__ b2,
                       const float* __restrict__ gg2, const float* __restrict__ be2,
                       const float* __restrict__ m2, const float* __restrict__ v2) {
    int o = threadIdx.x;
    if (o < 64) {
        float s0 = gg0[o] * rsqrtf(v0[o] + 1e-5f);
        for (int c = 0; c < 64; c++) g_w0f[o * 64 + c] = w0[o * 64 + c] * s0;
        g_b0f[o] = (b0[o] - m0[o]) * s0 + be0[o];
        float s1 = gg1[o] * rsqrtf(v1[o] + 1e-5f);
        for (int c = 0; c < 64; c++) g_w1f[o * 64 + c] = w1[o * 64 + c] * s1;
        g_b1f[o] = (b1[o] - m1[o]) * s1 + be1[o];
        for (int j = 0; j < 32; j++) {
            g_wp[o * 32 + j]        = pk2(g_w0f[o * 64 + 2 * j], g_w0f[o * 64 + 2 * j + 1]);
            g_wp[2048 + o * 32 + j] = pk2(g_w1f[o * 64 + 2 * j], g_w1f[o * 64 + 2 * j + 1]);
        }
    }
    float s2 = gg2[o] * rsqrtf(v2[o] + 1e-5f);
    for (int c = 0; c < 64; c++) g_w2f[o * 64 + c] = w2[o * 64 + c] * s2;
    g_b2f[o] = (b2[o] - m2[o]) * s2 + be2[o];
    for (int j = 0; j < 32; j++)
        g_wp[4096 + o * 32 + j] = pk2(g_w2f[o * 64 + 2 * j], g_w2f[o * 64 + 2 * j + 1]);
}

__global__ void k_pnorm(const float* __restrict__ points) {
    int i = blockIdx.x * blockDim.x + threadIdx.x;
    const float4* p = (const float4*)(points + (size_t)i * DD);
    float a0 = 0, a1 = 0, a2 = 0, a3 = 0;
#pragma unroll
    for (int u = 0; u < 16; u++) {
        float4 v = p[u];
        a0 = fmaf(v.x, v.x, a0); a1 = fmaf(v.y, v.y, a1);
        a2 = fmaf(v.z, v.z, a2); a3 = fmaf(v.w, v.w, a3);
    }
    g_pnorm[i] = (a0 + a1) + (a2 + a3);
}

__global__ void k_newxyz(const float* __restrict__ xyz, const int* __restrict__ sidx,
                         float* __restrict__ out) {
    int t = blockIdx.x * blockDim.x + threadIdx.x;
    if (t >= BB * SS * 3) return;
    int c = t % 3, s = (t / 3) % SS, b = t / (3 * SS);
    out[t] = xyz[((size_t)b * NN + sidx[s]) * 3 + c];
}

// ============================================================================
// k_mlp2: R12 winner + trailing grid-dependency sync (PDL ordering for k_gmax)
// ============================================================================
#define MLP_SMEMB (8192 * 8 + 32 * 129 * 4)

__device__ __forceinline__ void mlp_layer64(const unsigned long long* __restrict__ wsm,
                                            const float* __restrict__ bias,
                                            const unsigned long long* ip,
                                            unsigned long long* op) {
#pragma unroll 4
    for (int o2 = 0; o2 < 32; o2++) {
        const ulonglong2* r0 = (const ulonglong2*)(wsm + (2 * o2) * 32);
        const ulonglong2* r1 = (const ulonglong2*)(wsm + (2 * o2 + 1) * 32);
        unsigned long long a0 = 0ull, a1 = 0ull, b0 = 0ull, b1 = 0ull;
#pragma unroll
        for (int i = 0; i < 16; i++) {
            ulonglong2 w0v = r0[i];
            ulonglong2 w1v = r1[i];
            fmax2(a0, ip[2 * i], w0v.x);
            fmax2(a1, ip[2 * i + 1], w0v.y);
            fmax2(b0, ip[2 * i], w1v.x);
            fmax2(b1, ip[2 * i + 1], w1v.y);
        }
        float c0, c1, c2, c3;
        upk2(c0, c1, a0); upk2(c2, c3, a1);
        float s0 = (c0 + c1) + (c2 + c3);
        upk2(c0, c1, b0); upk2(c2, c3, b1);
        float s1 = (c0 + c1) + (c2 + c3);
        op[o2] = pk2(fmaxf(s0 + __ldg(bias + 2 * o2), 0.f),
                     fmaxf(s1 + __ldg(bias + 2 * o2 + 1), 0.f));
    }
}

__global__ void __launch_bounds__(128, 2) k_mlp2(const float* __restrict__ points) {
    extern __shared__ unsigned long long msm[];
    float* stg = (float*)(msm + 8192);
    const int tid = threadIdx.x;
    const size_t pt = (size_t)blockIdx.x * 128 + tid;

    for (int i = tid; i < 8192; i += 128) msm[i] = g_wp[i];

    unsigned long long xp[32];
    {
        const float4* x4 = (const float4*)(points + pt * DD);
#pragma unroll
        for (int u = 0; u < 16; u++) {
            float4 v = x4[u];
            xp[2 * u]     = pk2(v.x, v.y);
            xp[2 * u + 1] = pk2(v.z, v.w);
        }
    }
    __syncthreads();

    unsigned long long h0[32], h1[32];
    mlp_layer64(msm,        g_b0f, xp, h0);
    mlp_layer64(msm + 2048, g_b1f, h0, h1);

    const size_t obase = (size_t)blockIdx.x * 128 * 128;
    const int lane = tid & 31, grp = tid >> 5;
    for (int ch = 0; ch < 4; ch++) {
        __syncthreads();
#pragma unroll 2
        for (int o2 = 0; o2 < 16; o2++) {
            const int o = ch * 32 + 2 * o2;
            const ulonglong2* r0 = (const ulonglong2*)(msm + 4096 + o * 32);
            const ulonglong2* r1 = (const ulonglong2*)(msm + 4096 + (o + 1) * 32);
            unsigned long long a0 = 0ull, a1 = 0ull, b0 = 0ull, b1 = 0ull;
#pragma unroll
            for (int i = 0; i < 16; i++) {
                ulonglong2 w0v = r0[i];
                ulonglong2 w1v = r1[i];
                fmax2(a0, h1[2 * i], w0v.x);
                fmax2(a1, h1[2 * i + 1], w0v.y);
                fmax2(b0, h1[2 * i], w1v.x);
                fmax2(b1, h1[2 * i + 1], w1v.y);
            }
            float c0, c1, c2, c3;
            upk2(c0, c1, a0); upk2(c2, c3, a1);
            float s0 = (c0 + c1) + (c2 + c3);
            upk2(c0, c1, b0); upk2(c2, c3, b1);
            float s1 = (c0 + c1) + (c2 + c3);
            stg[(2 * o2 + 0) * 129 + tid] = fmaxf(s0 + __ldg(g_b2f + o), 0.f);
            stg[(2 * o2 + 1) * 129 + tid] = fmaxf(s1 + __ldg(g_b2f + o + 1), 0.f);
        }
        __syncthreads();
#pragma unroll 4
        for (int rr = grp; rr < 128; rr += 4) {
            g_h2[obase + (size_t)rr * 128 + ch * 32 + lane] = stg[lane * 129 + rr];
        }
    }

    // PDL ordering: k_mlp2 may start before k_dist8 finishes; ensure it cannot
    // COMPLETE before k_dist8 does, so the stream edge mlp->gmax covers dist->gmax.
#if __CUDA_ARCH__ >= 900
    cudaGridDependencySynchronize();
#endif
}

// ============================================================================
// k_dist8: byte-exact R14 winner + early PDL trigger
// ============================================================================
#define DS_SP  0u
#define DS_PN  16384u
#define DS_TV  16640u
#define DS_TI  33536u
#define DS_TOTB (50432 * 4)

struct TkMeta {
    float g0, g1, g2, g3;
    int   s0, s1, s2, s3;
    float thr;
    int   esl;
};
__device__ __forceinline__ void tk_init(TkMeta& M) {
    M.g0 = M.g1 = M.g2 = M.g3 = FLT_MAX;
    M.s0 = 0; M.s1 = 8; M.s2 = 16; M.s3 = 24;
    M.thr = FLT_MAX; M.esl = 0;
}
__device__ __forceinline__ void tk_insert(float* lv, int* li, float sc, int idx, TkMeta& M) {
    lv[M.esl] = sc; li[M.esl] = idx;
    const int g = M.esl >> 3;
    const int base = g << 3;
    float m = lv[base]; int ms = base;
#pragma unroll
    for (int j = 1; j < 8; j++) {
        float v = lv[base + j];
        if (v > m) { m = v; ms = base + j; }
    }
    if (g == 0)      { M.g0 = m; M.s0 = ms; }
    else if (g == 1) { M.g1 = m; M.s1 = ms; }
    else if (g == 2) { M.g2 = m; M.s2 = ms; }
    else             { M.g3 = m; M.s3 = ms; }
    float t = M.g0; int e = M.s0;
    if (M.g1 > t) { t = M.g1; e = M.s1; }
    if (M.g2 > t) { t = M.g2; e = M.s2; }
    if (M.g3 > t) { t = M.g3; e = M.s3; }
    M.thr = t; M.esl = e;
}

__global__ void __launch_bounds__(512, 1) k_dist8(const float* __restrict__ points,
                                                  const int* __restrict__ sidx) {
#if __CUDA_ARCH__ >= 900
    cudaTriggerProgrammaticLaunchCompletion();   // let k_mlp2 start on idle SMs now
#endif
    extern __shared__ float dsm[];
    const uint32_t sb = smem_u32(dsm);
    const int tid = threadIdx.x;
    const int qh = tid >> 7, l128 = tid & 127;
    const int b = blockIdx.y, s0 = blockIdx.x * 128;

    float* lv = dsm + DS_TV + tid * 33;
    int*   li = (int*)(dsm + DS_TI) + tid * 33;

    unsigned long long q2[32];
    {
        const int qi = __ldg(sidx + s0 + l128);
        const float4* qp = (const float4*)(points + ((size_t)b * NN + qi) * DD);
#pragma unroll
        for (int u = 0; u < 16; u++) {
            float4 v = qp[u];
            q2[2 * u]     = pk2(2.f * v.x, 2.f * v.y);
            q2[2 * u + 1] = pk2(2.f * v.z, 2.f * v.w);
        }
    }
#pragma unroll
    for (int j = 0; j < 32; j++) lv[j] = FLT_MAX;
    TkMeta M;
    tk_init(M);

    const float4* Pb = (const float4*)(points + (size_t)b * NN * DD);
    const float*  Pn = g_pnorm + b * NN;

    {
        uint32_t d = sb + DS_SP * 4 + tid * 16;
        const float4* s = Pb + tid;
#pragma unroll
        for (int i = 0; i < 4; i++) CPA16(d + i * 8192u, s + i * 512);
        if (tid < 128) CPA4(sb + (DS_PN + tid) * 4, Pn + tid);
    }
    CPA_COMMIT();

    for (int t = 0; t < 128; t++) {
        const int cur = t & 1;
        if (t < 127) {
            const int nxt = cur ^ 1;
            uint32_t d = sb + (DS_SP + nxt * 8192u) * 4 + tid * 16;
            const float4* s = Pb + (size_t)(t + 1) * 2048 + tid;
#pragma unroll
            for (int i = 0; i < 4; i++) CPA16(d + i * 8192u, s + i * 512);
            if (tid < 128) CPA4(sb + (DS_PN + nxt * 128u + tid) * 4, Pn + (t + 1) * 128 + tid);
        }
        CPA_COMMIT();
        CPA_WAIT1();
        __syncthreads();

        const float* tp = dsm + DS_SP + cur * 8192 + qh * 32 * 64;
        const float* pn = dsm + DS_PN + cur * 128 + qh * 32;
        const int ibase = t * 128 + qh * 32;
#pragma unroll 4
        for (int p = 0; p < 32; p++) {
            const ulonglong2* pv = (const ulonglong2*)(tp + p * 64);
            unsigned long long a0 = 0ull, a1 = 0ull;
#pragma unroll
            for (int i = 0; i < 16; i++) {
                ulonglong2 w = pv[i];
                fmax2(a0, q2[2 * i], w.x);
                fmax2(a1, q2[2 * i + 1], w.y);
            }
            a0 = addx2(a0, a1);
            float lo, hi;
            upk2(lo, hi, a0);
            float sc = pn[p] - (lo + hi);
            if (sc < M.thr) tk_insert(lv, li, sc, ibase + p, M);
        }
        __syncthreads();
    }

    if (tid < 128) {
        float* stv = dsm + DS_TV;
        int*   sti = (int*)(dsm + DS_TI);
        int* op = g_topk + ((size_t)b * SS + s0 + tid) * 32;
        for (int k = 0; k < 32; k++) {
            float m = FLT_MAX; int mi = 0x7fffffff, sel = 0;
#pragma unroll
            for (int h = 0; h < 4; h++) {
                const int base = (tid + 128 * h) * 33;
                for (int j = 0; j < 32; j++) {
                    float v = stv[base + j];
                    int   ii = sti[base + j];
                    if (v < m || (v == m && ii < mi)) { m = v; mi = ii; sel = base + j; }
                }
            }
            op[k] = mi;
            stv[sel] = FLT_MAX;
        }
    }
}

// ---------------- gather + channel max over the 32 neighbors ----------------
__global__ void k_gmax(float* __restrict__ out) {
    const int b = blockIdx.y, s = blockIdx.x, c = threadIdx.x;
    __shared__ int si[32];
    if (threadIdx.x < 32) si[threadIdx.x] = g_topk[((size_t)b * SS + s) * 32 + threadIdx.x];
    __syncthreads();
    const float* hb = g_h2 + (size_t)b * NN * 128;
    float m = -FLT_MAX;
#pragma unroll 8
    for (int j = 0; j < 32; j++) m = fmaxf(m, hb[(size_t)si[j] * 128 + c]);
    out[((size_t)b * SS + s) * 128 + c] = m;
}

// ---------------- launch ----------------
extern "C" void kernel_launch(void* const* d_in, const int* in_sizes, int n_in,
                              void* d_out, int out_size) {
    const float* xyz    = (const float*)d_in[0];
    const float* points = (const float*)d_in[1];
    const int*   sidx   = (const int*)d_in[2];

    float* out = (float*)d_out;
    float* out_xyz = nullptr;
    float* out_pts = out;
    if (out_size == BB * SS * 3 + BB * SS * 128) {
        out_xyz = out;
        out_pts = out + BB * SS * 3;
    }

    cudaFuncSetAttribute(k_dist8, cudaFuncAttributeMaxDynamicSharedMemorySize, DS_TOTB);
    cudaFuncSetAttribute(k_mlp2, cudaFuncAttributeMaxDynamicSharedMemorySize, MLP_SMEMB);

    k_prep<<<1, 128>>>((const float*)d_in[3], (const float*)d_in[4], (const float*)d_in[5],
                       (const float*)d_in[6], (const float*)d_in[7], (const float*)d_in[8],
                       (const float*)d_in[9], (const float*)d_in[10], (const float*)d_in[11],
                       (const float*)d_in[12], (const float*)d_in[13], (const float*)d_in[14],
                       (const float*)d_in[15], (const float*)d_in[16], (const float*)d_in[17],
                       (const float*)d_in[18], (const float*)d_in[19], (const float*)d_in[20]);
    k_pnorm<<<(BB * NN) / 256, 256>>>(points);
    if (out_xyz)
        k_newxyz<<<(BB * SS * 3 + 127) / 128, 128>>>(xyz, sidx, out_xyz);

    k_dist8<<<dim3(SS / 128, BB), 512, DS_TOTB>>>(points, sidx);

    // k_mlp2 overlaps k_dist8 on the 20 SMs k_dist8 leaves idle (PDL)
    {
        cudaLaunchConfig_t cfg = {};
        cfg.gridDim = dim3((BB * NN) / 128, 1, 1);
        cfg.blockDim = dim3(128, 1, 1);
        cfg.dynamicSmemBytes = MLP_SMEMB;
        cfg.stream = 0;
        cudaLaunchAttribute at[1];
        at[0].id = cudaLaunchAttributeProgrammaticStreamSerialization;
        at[0].val.programmaticStreamSerializationAllowed = 1;
        cfg.attrs = at;
        cfg.numAttrs = 1;
        cudaLaunchKernelEx(&cfg, k_mlp2, points);
    }

    k_gmax<<<dim3(SS, BB), 128>>>(out_pts);
}